// round 10
// baseline (speedup 1.0000x reference)
#include <cuda_runtime.h>

// Analytic collapse of SpatialAttentionLayer:
// V = ones(B,L,O,d)  =>
//   relu(V@Wk+bk) = rk[d] = relu(colsum(Wk)[d] + bk[d]), constant over (b,l,o)
//   _attention_net rows constant along softmax axis => phi=psi=theta=1/O,
//   and (uniform) @ rk-rows = rk.
// => M[b,l,o,d] = Σ_k relu(colsum(Wk)[d]+bk[d]), broadcast to [8,12,64,128].
//
// R9: single-barrier critical path. Phase 1 (LDG.128 + shfl row-reduce)
// writes 16 float4 partials to smem; ONE __syncthreads(); then EVERY thread
// combines via broadcast LDS + register-preloaded biases and stores its
// rows directly. Removes the second barrier + rvec smem round-trip (~110 cyc).
// Kernel duration is dominated by the ~5000-cycle launch ramp (T_ovh);
// body is a few hundred cycles.

#define D      128
#define NROWS  6144          // 8*12*64 output rows
#define GSPLIT 4             // column groups of 32 floats (one 128B line)
#define RSPLIT 32            // row splits of 192
#define NT     512           // 16 warps

__device__ __forceinline__ void add4(float4& a, const float4 b) {
    a.x += b.x; a.y += b.y; a.z += b.z; a.w += b.w;
}

__global__ void __launch_bounds__(NT, 1)
fused_kernel(const float* __restrict__ W1, const float* __restrict__ b1,
             const float* __restrict__ W2, const float* __restrict__ b2,
             const float* __restrict__ W3, const float* __restrict__ b3,
             const float* __restrict__ W4, const float* __restrict__ b4,
             float4* __restrict__ out) {
    __shared__ float4 part[16][8];   // [warp][quad] partial colsum (float4)

    const int tid  = threadIdx.x;
    const int w    = tid >> 5;                    // warp 0..15
    const int lane = tid & 31;
    const int g    = blockIdx.x & (GSPLIT - 1);   // column group
    const int s    = blockIdx.x >> 2;             // row split
    const int c0   = g * 32;                      // first column of group

    const int q = lane & 7;    // float4 quad within the 128B column group
    const int r = lane >> 3;   // 0..3 row-subgroup

    // ---- Preload biases for this thread's quad; latency hidden by phase 1.
    //      Lanes sharing q hit the same 16B — broadcast-friendly.
    const int boff = (c0 >> 2) + q;
    const float4 bq0 = reinterpret_cast<const float4*>(b1)[boff];
    const float4 bq1 = reinterpret_cast<const float4*>(b2)[boff];
    const float4 bq2 = reinterpret_cast<const float4*>(b3)[boff];
    const float4 bq3 = reinterpret_cast<const float4*>(b4)[boff];

    // ---- Phase 1: partial column sums for this 32-column group ----
    // warp w: matrix m = w>>2, rows [32*chunk, 32*chunk+32), chunk = w&3.
    {
        const int m     = w >> 2;
        const int chunk = w & 3;
        const float* __restrict__ W =
            (m == 0) ? W1 : (m == 1) ? W2 : (m == 2) ? W3 : W4;
        const float4* __restrict__ p =
            reinterpret_cast<const float4*>(W + (chunk * 32 + r * 8) * D + c0) + q;

        float4 v = p[0];
#pragma unroll
        for (int i = 1; i < 8; ++i) add4(v, p[i * (D / 4)]);

        // reduce across r (lane bits 3,4); afterwards every lane holds the
        // full 32-row partial for its quad q.
#pragma unroll
        for (int m2 = 8; m2 <= 16; m2 <<= 1) {
            v.x += __shfl_xor_sync(0xffffffffu, v.x, m2);
            v.y += __shfl_xor_sync(0xffffffffu, v.y, m2);
            v.z += __shfl_xor_sync(0xffffffffu, v.z, m2);
            v.w += __shfl_xor_sync(0xffffffffu, v.w, m2);
        }
        if (lane < 8) part[w][lane] = v;
    }
    __syncthreads();

    // ---- Combine in every thread: broadcast LDS (lanes sharing q read the
    //      same address) + register biases. ----
    float4 acc;
    {
        float4 a = part[0][q];
        add4(a, part[1][q]); add4(a, part[2][q]); add4(a, part[3][q]);
        acc.x = fmaxf(bq0.x + a.x, 0.f);
        acc.y = fmaxf(bq0.y + a.y, 0.f);
        acc.z = fmaxf(bq0.z + a.z, 0.f);
        acc.w = fmaxf(bq0.w + a.w, 0.f);
    }
    {
        float4 a = part[4][q];
        add4(a, part[5][q]); add4(a, part[6][q]); add4(a, part[7][q]);
        acc.x += fmaxf(bq1.x + a.x, 0.f);
        acc.y += fmaxf(bq1.y + a.y, 0.f);
        acc.z += fmaxf(bq1.z + a.z, 0.f);
        acc.w += fmaxf(bq1.w + a.w, 0.f);
    }
    {
        float4 a = part[8][q];
        add4(a, part[9][q]); add4(a, part[10][q]); add4(a, part[11][q]);
        acc.x += fmaxf(bq2.x + a.x, 0.f);
        acc.y += fmaxf(bq2.y + a.y, 0.f);
        acc.z += fmaxf(bq2.z + a.z, 0.f);
        acc.w += fmaxf(bq2.w + a.w, 0.f);
    }
    {
        float4 a = part[12][q];
        add4(a, part[13][q]); add4(a, part[14][q]); add4(a, part[15][q]);
        acc.x += fmaxf(bq3.x + a.x, 0.f);
        acc.y += fmaxf(bq3.y + a.y, 0.f);
        acc.z += fmaxf(bq3.z + a.z, 0.f);
        acc.w += fmaxf(bq3.w + a.w, 0.f);
    }

    // ---- Phase 2: broadcast-store 128B per row, 192 rows per block ----
    // warp stores rows row0 + {0,4,8} + r; each STG.128 wave = 4 full lines.
    const int row0 = s * (NROWS / RSPLIT) + w * 12 + r;
    float4* __restrict__ o = out + (long)row0 * (D / 4) + g * 8 + q;
#pragma unroll
    for (int it = 0; it < 3; ++it) {
        o[(long)it * 4 * (D / 4)] = acc;
    }
}

extern "C" void kernel_launch(void* const* d_in, const int* in_sizes, int n_in,
                              void* d_out, int out_size) {
    // metadata order: X(0), a{W1,b1,W2,b2,w3,b3}(1..6), b{...}(7..12),
    // c{...}(13..18), W1(19),b1(20),W2(21),b2(22),W3(23),b3(24),W4(25),b4(26)
    const float* W1 = (const float*)d_in[19];
    const float* b1 = (const float*)d_in[20];
    const float* W2 = (const float*)d_in[21];
    const float* b2 = (const float*)d_in[22];
    const float* W3 = (const float*)d_in[23];
    const float* b3 = (const float*)d_in[24];
    const float* W4 = (const float*)d_in[25];
    const float* b4 = (const float*)d_in[26];

    fused_kernel<<<GSPLIT * RSPLIT, NT>>>(W1, b1, W2, b2, W3, b3, W4, b4,
                                          (float4*)d_out);
}

// round 11
// speedup vs baseline: 1.1023x; 1.1023x over previous
#include <cuda_runtime.h>

// Analytic collapse of SpatialAttentionLayer:
// V = ones(B,L,O,d)  =>
//   relu(V@Wk+bk) = rk[d] = relu(colsum(Wk)[d] + bk[d]), constant over (b,l,o)
//   _attention_net rows constant along softmax axis => phi=psi=theta=1/O,
//   and (uniform) @ rk-rows = rk.
// => M[b,l,o,d] = Σ_k relu(colsum(Wk)[d]+bk[d]), broadcast to [8,12,64,128].
//
// R10 = R8 config (fastest measured kernel: 5.12us). Key budget facts learned:
//  - kernel time = ~4.3us launch ramp + ~0.8us body at micro-kernel DVFS
//  - per-thread instruction count is the binding body term (R9's all-thread
//    combine/bias-load regressed 0.5us despite removing a barrier)
// Per block (column-group g, row-split s): phase 1 LDG.128 column sums with
// shfl row-reduce; 8-thread combine with register-preloaded biases; 3 STG.128
// broadcast stores per thread. Grid = 4 col-groups x 32 row-splits.

#define D      128
#define NROWS  6144          // 8*12*64 output rows
#define GSPLIT 4             // column groups of 32 floats (one 128B line)
#define RSPLIT 32            // row splits of 192
#define NT     512           // 16 warps

__device__ __forceinline__ void add4(float4& a, const float4 b) {
    a.x += b.x; a.y += b.y; a.z += b.z; a.w += b.w;
}

__global__ void __launch_bounds__(NT, 1)
fused_kernel(const float* __restrict__ W1, const float* __restrict__ b1,
             const float* __restrict__ W2, const float* __restrict__ b2,
             const float* __restrict__ W3, const float* __restrict__ b3,
             const float* __restrict__ W4, const float* __restrict__ b4,
             float4* __restrict__ out) {
    __shared__ float4 part[16][8];   // [warp][quad] partial colsum (float4)
    __shared__ float4 rvec4[8];      // final r for this column group

    const int tid  = threadIdx.x;
    const int w    = tid >> 5;                    // warp 0..15
    const int lane = tid & 31;
    const int g    = blockIdx.x & (GSPLIT - 1);   // column group
    const int s    = blockIdx.x >> 2;             // row split
    const int c0   = g * 32;                      // first column of group

    const int q = lane & 7;    // float4 quad within the 128B column group
    const int r = lane >> 3;   // 0..3 row-subgroup

    // ---- Preload biases (combine threads only: tid<8 owns quad tid).
    //      Issued before phase 1 so their L2 latency is fully hidden.
    float4 bq0, bq1, bq2, bq3;
    if (tid < 8) {
        const int off = (c0 >> 2) + tid;          // float4 index
        bq0 = reinterpret_cast<const float4*>(b1)[off];
        bq1 = reinterpret_cast<const float4*>(b2)[off];
        bq2 = reinterpret_cast<const float4*>(b3)[off];
        bq3 = reinterpret_cast<const float4*>(b4)[off];
    }

    // ---- Phase 1: partial column sums for this 32-column group ----
    // warp w: matrix m = w>>2, rows [32*chunk, 32*chunk+32), chunk = w&3.
    // Thread loads 8 float4s; lanes with equal r cover one 128B line/row.
    {
        const int m     = w >> 2;
        const int chunk = w & 3;
        const float* __restrict__ W =
            (m == 0) ? W1 : (m == 1) ? W2 : (m == 2) ? W3 : W4;
        const float4* __restrict__ p =
            reinterpret_cast<const float4*>(W + (chunk * 32 + r * 8) * D + c0) + q;

        float4 v = p[0];
#pragma unroll
        for (int i = 1; i < 8; ++i) add4(v, p[i * (D / 4)]);

        // reduce across r (lane bits 3,4)
#pragma unroll
        for (int m2 = 8; m2 <= 16; m2 <<= 1) {
            v.x += __shfl_xor_sync(0xffffffffu, v.x, m2);
            v.y += __shfl_xor_sync(0xffffffffu, v.y, m2);
            v.z += __shfl_xor_sync(0xffffffffu, v.z, m2);
            v.w += __shfl_xor_sync(0xffffffffu, v.w, m2);
        }
        if (lane < 8) part[w][lane] = v;
    }
    __syncthreads();

    // ---- Combine (8 threads): r[c] = Σ_m relu(b_m[c] + colsum_m[c]) ----
    if (tid < 8) {
        float4 a0, acc;

        a0 = part[0][tid];
        add4(a0, part[1][tid]); add4(a0, part[2][tid]); add4(a0, part[3][tid]);
        acc.x = fmaxf(bq0.x + a0.x, 0.f);
        acc.y = fmaxf(bq0.y + a0.y, 0.f);
        acc.z = fmaxf(bq0.z + a0.z, 0.f);
        acc.w = fmaxf(bq0.w + a0.w, 0.f);

        a0 = part[4][tid];
        add4(a0, part[5][tid]); add4(a0, part[6][tid]); add4(a0, part[7][tid]);
        acc.x += fmaxf(bq1.x + a0.x, 0.f);
        acc.y += fmaxf(bq1.y + a0.y, 0.f);
        acc.z += fmaxf(bq1.z + a0.z, 0.f);
        acc.w += fmaxf(bq1.w + a0.w, 0.f);

        a0 = part[8][tid];
        add4(a0, part[9][tid]); add4(a0, part[10][tid]); add4(a0, part[11][tid]);
        acc.x += fmaxf(bq2.x + a0.x, 0.f);
        acc.y += fmaxf(bq2.y + a0.y, 0.f);
        acc.z += fmaxf(bq2.z + a0.z, 0.f);
        acc.w += fmaxf(bq2.w + a0.w, 0.f);

        a0 = part[12][tid];
        add4(a0, part[13][tid]); add4(a0, part[14][tid]); add4(a0, part[15][tid]);
        acc.x += fmaxf(bq3.x + a0.x, 0.f);
        acc.y += fmaxf(bq3.y + a0.y, 0.f);
        acc.z += fmaxf(bq3.z + a0.z, 0.f);
        acc.w += fmaxf(bq3.w + a0.w, 0.f);

        rvec4[tid] = acc;
    }
    __syncthreads();

    // ---- Phase 2: broadcast-store 128B per row, 192 rows per block ----
    // warp stores rows row0 + {0,4,8} + r; each STG.128 wave = 4 full lines.
    const float4 v = rvec4[q];
    const int row0 = s * (NROWS / RSPLIT) + w * 12 + r;
    float4* __restrict__ o = out + (long)row0 * (D / 4) + g * 8 + q;
#pragma unroll
    for (int it = 0; it < 3; ++it) {
        o[(long)it * 4 * (D / 4)] = v;
    }
}

extern "C" void kernel_launch(void* const* d_in, const int* in_sizes, int n_in,
                              void* d_out, int out_size) {
    // metadata order: X(0), a{W1,b1,W2,b2,w3,b3}(1..6), b{...}(7..12),
    // c{...}(13..18), W1(19),b1(20),W2(21),b2(22),W3(23),b3(24),W4(25),b4(26)
    const float* W1 = (const float*)d_in[19];
    const float* b1 = (const float*)d_in[20];
    const float* W2 = (const float*)d_in[21];
    const float* b2 = (const float*)d_in[22];
    const float* W3 = (const float*)d_in[23];
    const float* b3 = (const float*)d_in[24];
    const float* W4 = (const float*)d_in[25];
    const float* b4 = (const float*)d_in[26];

    fused_kernel<<<GSPLIT * RSPLIT, NT>>>(W1, b1, W2, b2, W3, b3, W4, b4,
                                          (float4*)d_out);
}

// round 12
// speedup vs baseline: 1.1449x; 1.0386x over previous
#include <cuda_runtime.h>

// Analytic collapse of SpatialAttentionLayer:
// V = ones(B,L,O,d)  =>
//   relu(V@Wk+bk) = rk[d] = relu(colsum(Wk)[d] + bk[d]), constant over (b,l,o)
//   _attention_net rows constant along softmax axis => phi=psi=theta=1/O,
//   and (uniform) @ rk-rows = rk.
// => M[b,l,o,d] = Σ_k relu(colsum(Wk)[d]+bk[d]), broadcast to [8,12,64,128].
//
// R11 = best body (R8: LDG.128 phase-1, shfl row-reduce, 8-thread combine
// with register-preloaded biases) x best grid (64 CTAs). Measured pattern:
// wall - kernel gap is ~0.8us at grid=64 vs ~1.6-2.0us at grid=128 (per-CTA
// replay overhead outside the ncu window), and that gap dwarfs the ~40cyc
// extra store issue from halving the grid.

#define D      128
#define NROWS  6144          // 8*12*64 output rows
#define GSPLIT 4             // column groups of 32 floats (one 128B line)
#define RSPLIT 16            // row splits of 384
#define NT     512           // 16 warps

__device__ __forceinline__ void add4(float4& a, const float4 b) {
    a.x += b.x; a.y += b.y; a.z += b.z; a.w += b.w;
}

__global__ void __launch_bounds__(NT, 1)
fused_kernel(const float* __restrict__ W1, const float* __restrict__ b1,
             const float* __restrict__ W2, const float* __restrict__ b2,
             const float* __restrict__ W3, const float* __restrict__ b3,
             const float* __restrict__ W4, const float* __restrict__ b4,
             float4* __restrict__ out) {
    __shared__ float4 part[16][8];   // [warp][quad] partial colsum (float4)
    __shared__ float4 rvec4[8];      // final r for this column group

    const int tid  = threadIdx.x;
    const int w    = tid >> 5;                    // warp 0..15
    const int lane = tid & 31;
    const int g    = blockIdx.x & (GSPLIT - 1);   // column group
    const int s    = blockIdx.x >> 2;             // row split
    const int c0   = g * 32;                      // first column of group

    const int q = lane & 7;    // float4 quad within the 128B column group
    const int r = lane >> 3;   // 0..3 row-subgroup

    // ---- Preload biases (combine threads only: tid<8 owns quad tid).
    //      Issued before phase 1 so their L2 latency is fully hidden.
    float4 bq0, bq1, bq2, bq3;
    if (tid < 8) {
        const int off = (c0 >> 2) + tid;          // float4 index
        bq0 = reinterpret_cast<const float4*>(b1)[off];
        bq1 = reinterpret_cast<const float4*>(b2)[off];
        bq2 = reinterpret_cast<const float4*>(b3)[off];
        bq3 = reinterpret_cast<const float4*>(b4)[off];
    }

    // ---- Phase 1: partial column sums for this 32-column group ----
    // warp w: matrix m = w>>2, rows [32*chunk, 32*chunk+32), chunk = w&3.
    // Thread loads 8 float4s; lanes with equal r cover one 128B line/row.
    {
        const int m     = w >> 2;
        const int chunk = w & 3;
        const float* __restrict__ W =
            (m == 0) ? W1 : (m == 1) ? W2 : (m == 2) ? W3 : W4;
        const float4* __restrict__ p =
            reinterpret_cast<const float4*>(W + (chunk * 32 + r * 8) * D + c0) + q;

        float4 v = p[0];
#pragma unroll
        for (int i = 1; i < 8; ++i) add4(v, p[i * (D / 4)]);

        // reduce across r (lane bits 3,4)
#pragma unroll
        for (int m2 = 8; m2 <= 16; m2 <<= 1) {
            v.x += __shfl_xor_sync(0xffffffffu, v.x, m2);
            v.y += __shfl_xor_sync(0xffffffffu, v.y, m2);
            v.z += __shfl_xor_sync(0xffffffffu, v.z, m2);
            v.w += __shfl_xor_sync(0xffffffffu, v.w, m2);
        }
        if (lane < 8) part[w][lane] = v;
    }
    __syncthreads();

    // ---- Combine (8 threads): r[c] = Σ_m relu(b_m[c] + colsum_m[c]) ----
    if (tid < 8) {
        float4 a0, acc;

        a0 = part[0][tid];
        add4(a0, part[1][tid]); add4(a0, part[2][tid]); add4(a0, part[3][tid]);
        acc.x = fmaxf(bq0.x + a0.x, 0.f);
        acc.y = fmaxf(bq0.y + a0.y, 0.f);
        acc.z = fmaxf(bq0.z + a0.z, 0.f);
        acc.w = fmaxf(bq0.w + a0.w, 0.f);

        a0 = part[4][tid];
        add4(a0, part[5][tid]); add4(a0, part[6][tid]); add4(a0, part[7][tid]);
        acc.x += fmaxf(bq1.x + a0.x, 0.f);
        acc.y += fmaxf(bq1.y + a0.y, 0.f);
        acc.z += fmaxf(bq1.z + a0.z, 0.f);
        acc.w += fmaxf(bq1.w + a0.w, 0.f);

        a0 = part[8][tid];
        add4(a0, part[9][tid]); add4(a0, part[10][tid]); add4(a0, part[11][tid]);
        acc.x += fmaxf(bq2.x + a0.x, 0.f);
        acc.y += fmaxf(bq2.y + a0.y, 0.f);
        acc.z += fmaxf(bq2.z + a0.z, 0.f);
        acc.w += fmaxf(bq2.w + a0.w, 0.f);

        a0 = part[12][tid];
        add4(a0, part[13][tid]); add4(a0, part[14][tid]); add4(a0, part[15][tid]);
        acc.x += fmaxf(bq3.x + a0.x, 0.f);
        acc.y += fmaxf(bq3.y + a0.y, 0.f);
        acc.z += fmaxf(bq3.z + a0.z, 0.f);
        acc.w += fmaxf(bq3.w + a0.w, 0.f);

        rvec4[tid] = acc;
    }
    __syncthreads();

    // ---- Phase 2: broadcast-store 128B per row, 384 rows per block ----
    // warp stores rows row0 + {0,4,...,20} + r; each STG.128 wave = 4 lines.
    const float4 v = rvec4[q];
    const int row0 = s * (NROWS / RSPLIT) + w * 24 + r;
    float4* __restrict__ o = out + (long)row0 * (D / 4) + g * 8 + q;
#pragma unroll
    for (int it = 0; it < 6; ++it) {
        o[(long)it * 4 * (D / 4)] = v;
    }
}

extern "C" void kernel_launch(void* const* d_in, const int* in_sizes, int n_in,
                              void* d_out, int out_size) {
    // metadata order: X(0), a{W1,b1,W2,b2,w3,b3}(1..6), b{...}(7..12),
    // c{...}(13..18), W1(19),b1(20),W2(21),b2(22),W3(23),b3(24),W4(25),b4(26)
    const float* W1 = (const float*)d_in[19];
    const float* b1 = (const float*)d_in[20];
    const float* W2 = (const float*)d_in[21];
    const float* b2 = (const float*)d_in[22];
    const float* W3 = (const float*)d_in[23];
    const float* b3 = (const float*)d_in[24];
    const float* W4 = (const float*)d_in[25];
    const float* b4 = (const float*)d_in[26];

    fused_kernel<<<GSPLIT * RSPLIT, NT>>>(W1, b1, W2, b2, W3, b3, W4, b4,
                                          (float4*)d_out);
}